// round 10
// baseline (speedup 1.0000x reference)
#include <cuda_runtime.h>
#include <cuda_fp16.h>
#include <cstdint>
#include <cmath>

// ---------------------------------------------------------------------------
// GraphSageLayer: B=4, N=4096, D_IN=128, REP=128, D_OUT=128
//
//  proj3_fused : CTA stages nodes tile + all 3 W in smem once; 3 GEMMs.
//  agg_both    : (1 launch, z=2) fp32 adj direct, cvt in staging, F-prefetch=2
//  final_fused : CTA stages upd tile + W_upd in smem once; tanh GEMM K=384.
// ---------------------------------------------------------------------------

__device__ __half g_in_rep [4l * 4096 * 128];
__device__ __half g_out_rep[4l * 4096 * 128];
__device__ float  g_upd    [4l * 4096 * 384];

__device__ __forceinline__ uint32_t pack2(float a, float b) {
    uint32_t r;
    asm("cvt.rn.f16x2.f32 %0, %1, %2;" : "=r"(r) : "f"(b), "f"(a));
    return r;
}
__device__ __forceinline__ void cp16(uint32_t dst, const void* src) {
    asm volatile("cp.async.cg.shared.global [%0], [%1], 16;" :: "r"(dst), "l"(src));
}
__device__ __forceinline__ void cp_commit() {
    asm volatile("cp.async.commit_group;");
}
__device__ __forceinline__ void cp_wait2() {
    asm volatile("cp.async.wait_group 2;");
}
__device__ __forceinline__ void ldsm4(uint32_t* r, uint32_t a) {
    asm volatile("ldmatrix.sync.aligned.m8n8.x4.shared.b16 {%0,%1,%2,%3}, [%4];"
        : "=r"(r[0]), "=r"(r[1]), "=r"(r[2]), "=r"(r[3]) : "r"(a));
}
__device__ __forceinline__ void ldsm4t(uint32_t* r, uint32_t a) {
    asm volatile("ldmatrix.sync.aligned.m8n8.x4.trans.shared.b16 {%0,%1,%2,%3}, [%4];"
        : "=r"(r[0]), "=r"(r[1]), "=r"(r[2]), "=r"(r[3]) : "r"(a));
}
__device__ __forceinline__ void mma16816(float* c, const uint32_t* a,
                                         uint32_t b0, uint32_t b1) {
    asm volatile(
        "mma.sync.aligned.m16n8k16.row.col.f32.f16.f16.f32 "
        "{%0,%1,%2,%3}, {%4,%5,%6,%7}, {%8,%9}, {%0,%1,%2,%3};\n"
        : "+f"(c[0]), "+f"(c[1]), "+f"(c[2]), "+f"(c[3])
        : "r"(a[0]), "r"(a[1]), "r"(a[2]), "r"(a[3]), "r"(b0), "r"(b1));
}

// stage a fp32 row-major [rows][K] tile into fp16 smem with ROWB-byte rows.
// Each thread: row = tid>>1, handles K/2 cols at half-offset (tid&1)*K/2.
template<int K>
__device__ __forceinline__ void stage_f16(const float* __restrict__ src, int lds,
                                          char* dst, int rowB, int tid)
{
    const int row = tid >> 1, h = tid & 1;
    const float4* s = (const float4*)(src + (long)row * lds + h * (K / 2));
    char* d = dst + row * rowB + h * K;   // K/2 halves = K bytes
    #pragma unroll
    for (int j = 0; j < K / 16; j++) {
        float4 v0 = s[2 * j], v1 = s[2 * j + 1];
        *(uint4*)(d + j * 16) = make_uint4(pack2(v0.x, v0.y), pack2(v0.z, v0.w),
                                           pack2(v1.x, v1.y), pack2(v1.z, v1.w));
    }
}

// ===========================================================================
// proj3_fused: grid 128, 256 thr. smem: A(nodes)@0, W0@34816, W1@69632, W2@104448
// CTA computes 128 rows x 128 cols for all three projections.
// ===========================================================================
__global__ __launch_bounds__(256)
void proj3_fused(const float* __restrict__ nodes,
                 const float* __restrict__ W_in,   const float* __restrict__ b_in,
                 const float* __restrict__ W_node, const float* __restrict__ b_node,
                 const float* __restrict__ W_out,  const float* __restrict__ b_out,
                 __half* __restrict__ in_rep, __half* __restrict__ out_rep,
                 float* __restrict__ upd)
{
    extern __shared__ char sm[];
    const int tid  = threadIdx.x;
    const int lane = tid & 31;
    const int warp = tid >> 5;
    const int wm = warp >> 2, wn = warp & 3;
    const int g = lane >> 2, t = lane & 3;
    const int m0 = blockIdx.x * 128;

    stage_f16<128>(nodes + (long)m0 * 128, 128, sm, 272, tid);
    stage_f16<128>(W_in,   128, sm + 34816,  272, tid);
    stage_f16<128>(W_node, 128, sm + 69632,  272, tid);
    stage_f16<128>(W_out,  128, sm + 104448, 272, tid);
    __syncthreads();

    const uint32_t sA = (uint32_t)__cvta_generic_to_shared(sm);

    #pragma unroll 1
    for (int z = 0; z < 3; z++) {
        const uint32_t sW = sA + 34816 * (1 + z);
        const float* bias = (z == 0) ? b_in : (z == 1) ? b_node : b_out;

        float acc[4][4][4];
        #pragma unroll
        for (int i = 0; i < 4; i++)
            #pragma unroll
            for (int j = 0; j < 4; j++)
                #pragma unroll
                for (int l = 0; l < 4; l++) acc[i][j][l] = 0.f;

        #pragma unroll
        for (int k = 0; k < 8; k++) {
            const uint32_t kOff = ((lane >> 4) + 2 * k) * 16;
            uint32_t aF[4][4], bR[2][4];
            #pragma unroll
            for (int mt = 0; mt < 4; mt++)
                ldsm4(aF[mt], sA + (wm * 64 + mt * 16 + (lane & 15)) * 272 + kOff);
            #pragma unroll
            for (int i = 0; i < 2; i++)
                ldsm4(bR[i], sW + (wn * 32 + i * 16 + (lane & 15)) * 272 + kOff);
            #pragma unroll
            for (int mt = 0; mt < 4; mt++)
                #pragma unroll
                for (int nt = 0; nt < 4; nt++)
                    mma16816(acc[mt][nt], aF[mt],
                             bR[nt >> 1][nt & 1], bR[nt >> 1][(nt & 1) + 2]);
        }

        #pragma unroll
        for (int mt = 0; mt < 4; mt++)
            #pragma unroll
            for (int nt = 0; nt < 4; nt++) {
                const int row = m0 + wm * 64 + mt * 16 + g;
                const int col = wn * 32 + nt * 8 + 2 * t;
                const float b0 = __ldg(bias + col), b1 = __ldg(bias + col + 1);
                float x0 = acc[mt][nt][0] + b0, x1 = acc[mt][nt][1] + b1;
                float x2 = acc[mt][nt][2] + b0, x3 = acc[mt][nt][3] + b1;
                x0 = x0 > 0.f ? x0 : expm1f(x0);
                x1 = x1 > 0.f ? x1 : expm1f(x1);
                x2 = x2 > 0.f ? x2 : expm1f(x2);
                x3 = x3 > 0.f ? x3 : expm1f(x3);
                if (z == 1) {
                    *(float2*)&upd[(long)row       * 384 + 128 + col] = make_float2(x0, x1);
                    *(float2*)&upd[(long)(row + 8) * 384 + 128 + col] = make_float2(x2, x3);
                } else {
                    __half* D = (z == 0) ? in_rep : out_rep;
                    *(uint32_t*)&D[(long)row       * 128 + col] = pack2(x0, x1);
                    *(uint32_t*)&D[(long)(row + 8) * 128 + col] = pack2(x2, x3);
                }
            }
    }
}

// ===========================================================================
// final_fused: grid 128, 256 thr. smem: A(upd)@0 (128x784), W@100352 (128x784)
// out = tanh(upd @ W_upd^T + b_upd), K=384.
// ===========================================================================
__global__ __launch_bounds__(256)
void final_fused(const float* __restrict__ upd, const float* __restrict__ W,
                 const float* __restrict__ bias, float* __restrict__ out)
{
    extern __shared__ char sm[];
    const int tid  = threadIdx.x;
    const int lane = tid & 31;
    const int warp = tid >> 5;
    const int wm = warp >> 2, wn = warp & 3;
    const int g = lane >> 2, t = lane & 3;
    const int m0 = blockIdx.x * 128;

    stage_f16<384>(upd + (long)m0 * 384, 384, sm, 784, tid);
    stage_f16<384>(W, 384, sm + 100352, 784, tid);
    __syncthreads();

    const uint32_t sA = (uint32_t)__cvta_generic_to_shared(sm);
    const uint32_t sW = sA + 100352;

    float acc[4][4][4];
    #pragma unroll
    for (int i = 0; i < 4; i++)
        #pragma unroll
        for (int j = 0; j < 4; j++)
            #pragma unroll
            for (int l = 0; l < 4; l++) acc[i][j][l] = 0.f;

    #pragma unroll 1
    for (int k = 0; k < 24; k++) {
        const uint32_t kOff = ((lane >> 4) + 2 * k) * 16;
        uint32_t aF[4][4], bR[2][4];
        #pragma unroll
        for (int mt = 0; mt < 4; mt++)
            ldsm4(aF[mt], sA + (wm * 64 + mt * 16 + (lane & 15)) * 784 + kOff);
        #pragma unroll
        for (int i = 0; i < 2; i++)
            ldsm4(bR[i], sW + (wn * 32 + i * 16 + (lane & 15)) * 784 + kOff);
        #pragma unroll
        for (int mt = 0; mt < 4; mt++)
            #pragma unroll
            for (int nt = 0; nt < 4; nt++)
                mma16816(acc[mt][nt], aF[mt],
                         bR[nt >> 1][nt & 1], bR[nt >> 1][(nt & 1) + 2]);
    }

    #pragma unroll
    for (int mt = 0; mt < 4; mt++)
        #pragma unroll
        for (int nt = 0; nt < 4; nt++) {
            const int row = m0 + wm * 64 + mt * 16 + g;
            const int col = wn * 32 + nt * 8 + 2 * t;
            const float b0 = __ldg(bias + col), b1 = __ldg(bias + col + 1);
            float x0 = tanhf(acc[mt][nt][0] + b0), x1 = tanhf(acc[mt][nt][1] + b1);
            float x2 = tanhf(acc[mt][nt][2] + b0), x3 = tanhf(acc[mt][nt][3] + b1);
            *(float2*)&out[(long)row       * 128 + col] = make_float2(x0, x1);
            *(float2*)&out[(long)(row + 8) * 128 + col] = make_float2(x2, x3);
        }
}

// ===========================================================================
// Aggregation: CTA 128x128, K=4096, BK=32.
//  adj: fp32 LDG(__ldcs) -> cvt(x4096) -> STS fp16, 2 smem bufs, reg-prefetch=2.
//  rep: fp16 cp.async, 4-stage.
// ===========================================================================
template<bool OUTT>
__device__ __forceinline__ void agg_body(
    const float* __restrict__ adj, const __half* __restrict__ rep,
    float* __restrict__ upd, char* smem)
{
    const int tid  = threadIdx.x;
    const int lane = tid & 31;
    const int warp = tid >> 5;
    const int wm   = warp >> 2;
    const int wn   = warp & 3;
    const int g    = lane >> 2;
    const int t    = lane & 3;
    const int tile0 = blockIdx.x * 128;
    const long b   = blockIdx.y;

    const float*  adjB = adj + b * (4096l * 4096);
    const __half* repB = rep + b * (4096l * 128);
    float*        updB = upd + b * (4096l * 384);

    const uint32_t smBase = (uint32_t)__cvta_generic_to_shared(smem);
    const uint32_t sF0 = OUTT ? (smBase + 34816) : smBase;
    const int      FSTRIDE = OUTT ? 8704 : 10240;
    const uint32_t sR0 = OUTT ? smBase : (smBase + 20480);

    float acc[4][4][4];
    #pragma unroll
    for (int i = 0; i < 4; i++)
        #pragma unroll
        for (int j = 0; j < 4; j++)
            #pragma unroll
            for (int l = 0; l < 4; l++) acc[i][j][l] = 0.f;

    const int f_row = OUTT ? (tid >> 3) : (tid >> 1);
    const int f_ch  = OUTT ? (tid & 7)  : (tid & 1);
    const float* fSrcBase = OUTT
        ? (adjB + (long)f_row * 4096 + tile0 + f_ch * 16)
        : (adjB + (long)(tile0 + f_row) * 4096 + f_ch * 16);
    const uint32_t fDst = (OUTT ? f_row * 272 : f_row * 80) + f_ch * 32;

    float4 fv[2][4];
    auto ldF = [&](int k0, int s) {
        const float* p = OUTT ? (fSrcBase + (long)k0 * 4096) : (fSrcBase + k0);
        #pragma unroll
        for (int i = 0; i < 4; i++) fv[s][i] = __ldcs((const float4*)p + i);
    };
    auto stsF = [&](int buf, int s) {
        uint32_t w[8];
        #pragma unroll
        for (int i = 0; i < 4; i++) {
            w[2 * i]     = pack2(fv[s][i].x * 4096.f, fv[s][i].y * 4096.f);
            w[2 * i + 1] = pack2(fv[s][i].z * 4096.f, fv[s][i].w * 4096.f);
        }
        const uint32_t d = (sF0 - smBase) + buf * FSTRIDE + fDst;
        *(uint4*)(smem + d)      = make_uint4(w[0], w[1], w[2], w[3]);
        *(uint4*)(smem + d + 16) = make_uint4(w[4], w[5], w[6], w[7]);
    };

    const int r_k  = tid >> 4;
    const int r_nc = tid & 15;
    auto cpR = [&](int st, int k0) {
        const uint32_t sR = sR0 + st * 8704;
        cp16(sR + r_k * 272 + r_nc * 16,        repB + (long)(k0 + r_k) * 128 + r_nc * 8);
        cp16(sR + (r_k + 16) * 272 + r_nc * 16, repB + (long)(k0 + r_k + 16) * 128 + r_nc * 8);
    };

    auto compute = [&](int kt) {
        const uint32_t sA = OUTT ? (sR0 + (kt & 3) * 8704) : (sF0 + (kt & 1) * FSTRIDE);
        const uint32_t sB = OUTT ? (sF0 + (kt & 1) * FSTRIDE) : (sR0 + (kt & 3) * 8704);
        #pragma unroll
        for (int ks = 0; ks < 2; ks++) {
            uint32_t aF[4][4], bF[2][4];
            #pragma unroll
            for (int mt = 0; mt < 4; mt++) {
                if (!OUTT) {
                    ldsm4(aF[mt], sA + (wm * 64 + mt * 16 + (lane & 15)) * 80
                                     + ((lane >> 4) + 2 * ks) * 16);
                } else {
                    ldsm4t(aF[mt], sA + ((lane & 7) + (lane >> 4) * 8 + 16 * ks) * 272
                                      + (wm * 64 + mt * 16 + ((lane >> 3) & 1) * 8) * 2);
                }
            }
            #pragma unroll
            for (int nt = 0; nt < 2; nt++)
                ldsm4t(bF[nt], sB + ((lane & 15) + 16 * ks) * 272
                                  + wn * 64 + nt * 32 + (lane >> 4) * 16);
            #pragma unroll
            for (int mt = 0; mt < 4; mt++)
                #pragma unroll
                for (int n8 = 0; n8 < 4; n8++)
                    mma16816(acc[mt][n8], aF[mt],
                             bF[n8 >> 1][(n8 & 1) * 2], bF[n8 >> 1][(n8 & 1) * 2 + 1]);
        }
    };

    // prologue: F prefetch distance 2, R 3 stages in flight
    ldF(0, 0);
    ldF(32, 1);
    #pragma unroll
    for (int s = 0; s < 3; s++) { cpR(s, s * 32); cp_commit(); }

    #pragma unroll 1
    for (int kt = 0; kt < 128; kt++) {
        stsF(kt & 1, kt & 1);
        cp_wait2();
        __syncthreads();
        if (kt + 2 < 128) ldF((kt + 2) * 32, kt & 1);
        const int nx = kt + 3;
        if (nx < 128) cpR(nx & 3, nx * 32);
        cp_commit();
        compute(kt);
    }

    const float s = 1.f / 4096.f;
    if (!OUTT) {
        #pragma unroll
        for (int mt = 0; mt < 4; mt++)
            #pragma unroll
            for (int n8 = 0; n8 < 4; n8++) {
                const int row = tile0 + wm * 64 + mt * 16 + g;
                const int col = wn * 32 + n8 * 8 + 2 * t;
                *(float2*)&updB[(long)row * 384 + col] =
                    make_float2(acc[mt][n8][0] * s, acc[mt][n8][1] * s);
                *(float2*)&updB[(long)(row + 8) * 384 + col] =
                    make_float2(acc[mt][n8][2] * s, acc[mt][n8][3] * s);
            }
    } else {
        __syncthreads();
        float* fsm = (float*)smem;   // [v][132] = 67584 B
        #pragma unroll
        for (int mt = 0; mt < 4; mt++)
            #pragma unroll
            for (int n8 = 0; n8 < 4; n8++) {
                const int v = wm * 64 + mt * 16 + g;
                const int j = wn * 32 + n8 * 8 + 2 * t;
                fsm[v * 132 + j]           = acc[mt][n8][0] * s;
                fsm[v * 132 + j + 1]       = acc[mt][n8][1] * s;
                fsm[(v + 8) * 132 + j]     = acc[mt][n8][2] * s;
                fsm[(v + 8) * 132 + j + 1] = acc[mt][n8][3] * s;
            }
        __syncthreads();
        const int j  = tid >> 1;
        const int vb = (tid & 1) * 64;
        float* dst = &updB[(long)(tile0 + j) * 384 + 256 + vb];
        #pragma unroll
        for (int i = 0; i < 16; i++) {
            const int v = vb + i * 4;
            ((float4*)dst)[i] = make_float4(
                fsm[v * 132 + j],       fsm[(v + 1) * 132 + j],
                fsm[(v + 2) * 132 + j], fsm[(v + 3) * 132 + j]);
        }
    }
}

__global__ __launch_bounds__(256, 2)
void agg_both(const float* __restrict__ adj,
              const __half* __restrict__ in_rep,
              const __half* __restrict__ out_rep,
              float* __restrict__ upd)
{
    extern __shared__ char smem[];
    if (blockIdx.z == 0) agg_body<false>(adj, in_rep,  upd, smem);
    else                 agg_body<true >(adj, out_rep, upd, smem);
}

// ===========================================================================
extern "C" void kernel_launch(void* const* d_in, const int* in_sizes, int n_in,
                              void* d_out, int out_size)
{
    const float* nodes  = (const float*)d_in[0];
    const float* adj    = (const float*)d_in[1];
    const float* W_in   = (const float*)d_in[2];
    const float* b_in   = (const float*)d_in[3];
    const float* W_out  = (const float*)d_in[4];
    const float* b_out  = (const float*)d_in[5];
    const float* W_node = (const float*)d_in[6];
    const float* b_node = (const float*)d_in[7];
    const float* W_upd  = (const float*)d_in[8];
    const float* b_upd  = (const float*)d_in[9];
    float* out = (float*)d_out;

    __half *in_rep, *out_rep;
    float *upd;
    cudaGetSymbolAddress((void**)&in_rep,  g_in_rep);
    cudaGetSymbolAddress((void**)&out_rep, g_out_rep);
    cudaGetSymbolAddress((void**)&upd,     g_upd);

    const int SMEM_PROJ  = 4 * 34816;     // 139264
    const int SMEM_AGG   = 128 * 132 * 4; // 67584
    const int SMEM_FINAL = 2 * 100352;    // 200704
    cudaFuncSetAttribute(proj3_fused,
                         cudaFuncAttributeMaxDynamicSharedMemorySize, SMEM_PROJ);
    cudaFuncSetAttribute(agg_both,
                         cudaFuncAttributeMaxDynamicSharedMemorySize, SMEM_AGG);
    cudaFuncSetAttribute(final_fused,
                         cudaFuncAttributeMaxDynamicSharedMemorySize, SMEM_FINAL);

    // 1) three ELU projections, weights resident in smem
    proj3_fused<<<128, 256, SMEM_PROJ>>>(nodes, W_in, b_in, W_node, b_node,
                                         W_out, b_out, in_rep, out_rep, upd);

    // 2+3) both aggregations, one launch, fp32 adj direct (prefetch=2)
    agg_both<<<dim3(32, 4, 2), 256, SMEM_AGG>>>(adj, in_rep, out_rep, upd);

    // 4) out = tanh(upd @ W_upd^T + b_upd)
    final_fused<<<128, 256, SMEM_FINAL>>>(upd, W_upd, b_upd, out);
}

// round 11
// speedup vs baseline: 1.4960x; 1.4960x over previous
#include <cuda_runtime.h>
#include <cuda_fp16.h>
#include <cstdint>
#include <cmath>

// ---------------------------------------------------------------------------
// GraphSageLayer: B=4, N=4096, D_IN=128, REP=128, D_OUT=128
//
//  proj3_v2 : grid (128,1,3); CTA stages nodes tile + ONE W (69.6KB, 2 CTA/SM);
//             K=128 resident, single barrier. ELU epilogue.
//  agg_both : (1 launch, z=2) fp32 adj direct, cvt in staging (R9 loop,
//             ldF hoisted above the barrier).
//  final    : R9 gemm_core tanh GEMM (unchanged).
// ---------------------------------------------------------------------------

__device__ __half g_in_rep [4l * 4096 * 128];
__device__ __half g_out_rep[4l * 4096 * 128];
__device__ float  g_upd    [4l * 4096 * 384];

__device__ __forceinline__ uint32_t pack2(float a, float b) {
    uint32_t r;
    asm("cvt.rn.f16x2.f32 %0, %1, %2;" : "=r"(r) : "f"(b), "f"(a));
    return r;
}
__device__ __forceinline__ void cp16(uint32_t dst, const void* src) {
    asm volatile("cp.async.cg.shared.global [%0], [%1], 16;" :: "r"(dst), "l"(src));
}
__device__ __forceinline__ void cp_commit() {
    asm volatile("cp.async.commit_group;");
}
__device__ __forceinline__ void cp_wait2() {
    asm volatile("cp.async.wait_group 2;");
}
__device__ __forceinline__ void ldsm4(uint32_t* r, uint32_t a) {
    asm volatile("ldmatrix.sync.aligned.m8n8.x4.shared.b16 {%0,%1,%2,%3}, [%4];"
        : "=r"(r[0]), "=r"(r[1]), "=r"(r[2]), "=r"(r[3]) : "r"(a));
}
__device__ __forceinline__ void ldsm4t(uint32_t* r, uint32_t a) {
    asm volatile("ldmatrix.sync.aligned.m8n8.x4.trans.shared.b16 {%0,%1,%2,%3}, [%4];"
        : "=r"(r[0]), "=r"(r[1]), "=r"(r[2]), "=r"(r[3]) : "r"(a));
}
__device__ __forceinline__ void mma16816(float* c, const uint32_t* a,
                                         uint32_t b0, uint32_t b1) {
    asm volatile(
        "mma.sync.aligned.m16n8k16.row.col.f32.f16.f16.f32 "
        "{%0,%1,%2,%3}, {%4,%5,%6,%7}, {%8,%9}, {%0,%1,%2,%3};\n"
        : "+f"(c[0]), "+f"(c[1]), "+f"(c[2]), "+f"(c[3])
        : "r"(a[0]), "r"(a[1]), "r"(a[2]), "r"(a[3]), "r"(b0), "r"(b1));
}

// stage a fp32 row-major [128][K] tile into fp16 smem, rowB-byte rows.
// 256 threads: row = tid>>1, half = tid&1. Interleaved ld/cvt/sts (low regs).
template<int K>
__device__ __forceinline__ void stage_f16(const float* __restrict__ src, int lds,
                                          char* dst, int rowB, int tid)
{
    const int row = tid >> 1, h = tid & 1;
    const float4* s = (const float4*)(src + (long)row * lds + h * (K / 2));
    char* d = dst + row * rowB + h * K;
    #pragma unroll
    for (int j = 0; j < K / 16; j++) {
        float4 v0 = s[2 * j], v1 = s[2 * j + 1];
        *(uint4*)(d + j * 16) = make_uint4(pack2(v0.x, v0.y), pack2(v0.z, v0.w),
                                           pack2(v1.x, v1.y), pack2(v1.z, v1.w));
    }
}

// ===========================================================================
// proj3_v2: grid (128,1,3), 256 thr, smem 69632 (A@0, W@34816), 2 CTA/SM.
// z selects (W, bias, destination). K=128 resident; ldsm non-trans both ops.
// ===========================================================================
__global__ __launch_bounds__(256, 2)
void proj3_v2(const float* __restrict__ nodes,
              const float* __restrict__ W_in,   const float* __restrict__ b_in,
              const float* __restrict__ W_node, const float* __restrict__ b_node,
              const float* __restrict__ W_out,  const float* __restrict__ b_out,
              __half* __restrict__ in_rep, __half* __restrict__ out_rep,
              float* __restrict__ upd)
{
    extern __shared__ char sm[];
    const int tid  = threadIdx.x;
    const int lane = tid & 31;
    const int warp = tid >> 5;
    const int wm = warp >> 2, wn = warp & 3;
    const int g = lane >> 2, t = lane & 3;
    const int m0 = blockIdx.x * 128;
    const int z  = blockIdx.z;

    const float* W    = (z == 0) ? W_in : (z == 1) ? W_node : W_out;
    const float* bias = (z == 0) ? b_in : (z == 1) ? b_node : b_out;

    stage_f16<128>(nodes + (long)m0 * 128, 128, sm, 272, tid);
    stage_f16<128>(W, 128, sm + 34816, 272, tid);
    __syncthreads();

    const uint32_t sA = (uint32_t)__cvta_generic_to_shared(sm);
    const uint32_t sW = sA + 34816;

    float acc[4][4][4];
    #pragma unroll
    for (int i = 0; i < 4; i++)
        #pragma unroll
        for (int j = 0; j < 4; j++)
            #pragma unroll
            for (int l = 0; l < 4; l++) acc[i][j][l] = 0.f;

    #pragma unroll
    for (int k = 0; k < 8; k++) {
        const uint32_t kOff = ((lane >> 4) + 2 * k) * 16;
        uint32_t aF[4][4], bR[2][4];
        #pragma unroll
        for (int mt = 0; mt < 4; mt++)
            ldsm4(aF[mt], sA + (wm * 64 + mt * 16 + (lane & 15)) * 272 + kOff);
        #pragma unroll
        for (int i = 0; i < 2; i++)
            ldsm4(bR[i], sW + (wn * 32 + i * 16 + (lane & 15)) * 272 + kOff);
        #pragma unroll
        for (int mt = 0; mt < 4; mt++)
            #pragma unroll
            for (int nt = 0; nt < 4; nt++)
                mma16816(acc[mt][nt], aF[mt],
                         bR[nt >> 1][nt & 1], bR[nt >> 1][(nt & 1) + 2]);
    }

    #pragma unroll
    for (int mt = 0; mt < 4; mt++)
        #pragma unroll
        for (int nt = 0; nt < 4; nt++) {
            const int row = m0 + wm * 64 + mt * 16 + g;
            const int col = wn * 32 + nt * 8 + 2 * t;
            const float b0 = __ldg(bias + col), b1 = __ldg(bias + col + 1);
            float x0 = acc[mt][nt][0] + b0, x1 = acc[mt][nt][1] + b1;
            float x2 = acc[mt][nt][2] + b0, x3 = acc[mt][nt][3] + b1;
            x0 = x0 > 0.f ? x0 : expm1f(x0);
            x1 = x1 > 0.f ? x1 : expm1f(x1);
            x2 = x2 > 0.f ? x2 : expm1f(x2);
            x3 = x3 > 0.f ? x3 : expm1f(x3);
            if (z == 1) {
                *(float2*)&upd[(long)row       * 384 + 128 + col] = make_float2(x0, x1);
                *(float2*)&upd[(long)(row + 8) * 384 + 128 + col] = make_float2(x2, x3);
            } else {
                __half* D = (z == 0) ? in_rep : out_rep;
                *(uint32_t*)&D[(long)row       * 128 + col] = pack2(x0, x1);
                *(uint32_t*)&D[(long)(row + 8) * 128 + col] = pack2(x2, x3);
            }
        }
}

// ===========================================================================
// Aggregation (R9 loop, ldF hoisted above the barrier): CTA 128x128, BK=32.
//  adj: fp32 LDG -> cvt(x4096) -> STS fp16, 2 smem bufs, reg-prefetch dist 1.
//  rep: fp16 cp.async, 4-stage.
// ===========================================================================
template<bool OUTT>
__device__ __forceinline__ void agg_body(
    const float* __restrict__ adj, const __half* __restrict__ rep,
    float* __restrict__ upd, char* smem)
{
    const int tid  = threadIdx.x;
    const int lane = tid & 31;
    const int warp = tid >> 5;
    const int wm   = warp >> 2;
    const int wn   = warp & 3;
    const int g    = lane >> 2;
    const int t    = lane & 3;
    const int tile0 = blockIdx.x * 128;
    const long b   = blockIdx.y;

    const float*  adjB = adj + b * (4096l * 4096);
    const __half* repB = rep + b * (4096l * 128);
    float*        updB = upd + b * (4096l * 384);

    const uint32_t smBase = (uint32_t)__cvta_generic_to_shared(smem);
    const uint32_t sF0 = OUTT ? (smBase + 34816) : smBase;
    const int      FSTRIDE = OUTT ? 8704 : 10240;
    const uint32_t sR0 = OUTT ? smBase : (smBase + 20480);

    float acc[4][4][4];
    #pragma unroll
    for (int i = 0; i < 4; i++)
        #pragma unroll
        for (int j = 0; j < 4; j++)
            #pragma unroll
            for (int l = 0; l < 4; l++) acc[i][j][l] = 0.f;

    const int f_row = OUTT ? (tid >> 3) : (tid >> 1);
    const int f_ch  = OUTT ? (tid & 7)  : (tid & 1);
    const float* fSrcBase = OUTT
        ? (adjB + (long)f_row * 4096 + tile0 + f_ch * 16)
        : (adjB + (long)(tile0 + f_row) * 4096 + f_ch * 16);
    const uint32_t fDst = (OUTT ? f_row * 272 : f_row * 80) + f_ch * 32;

    float4 fv[4];
    auto ldF = [&](int k0) {
        const float* p = OUTT ? (fSrcBase + (long)k0 * 4096) : (fSrcBase + k0);
        #pragma unroll
        for (int i = 0; i < 4; i++) fv[i] = ((const float4*)p)[i];
    };
    auto stsF = [&](int buf) {
        uint32_t w[8];
        #pragma unroll
        for (int i = 0; i < 4; i++) {
            w[2 * i]     = pack2(fv[i].x * 4096.f, fv[i].y * 4096.f);
            w[2 * i + 1] = pack2(fv[i].z * 4096.f, fv[i].w * 4096.f);
        }
        const uint32_t d = (sF0 - smBase) + buf * FSTRIDE + fDst;
        *(uint4*)(smem + d)      = make_uint4(w[0], w[1], w[2], w[3]);
        *(uint4*)(smem + d + 16) = make_uint4(w[4], w[5], w[6], w[7]);
    };

    const int r_k  = tid >> 4;
    const int r_nc = tid & 15;
    auto cpR = [&](int st, int k0) {
        const uint32_t sR = sR0 + st * 8704;
        cp16(sR + r_k * 272 + r_nc * 16,        repB + (long)(k0 + r_k) * 128 + r_nc * 8);
        cp16(sR + (r_k + 16) * 272 + r_nc * 16, repB + (long)(k0 + r_k + 16) * 128 + r_nc * 8);
    };

    auto compute = [&](int kt) {
        const uint32_t sA = OUTT ? (sR0 + (kt & 3) * 8704) : (sF0 + (kt & 1) * FSTRIDE);
        const uint32_t sB = OUTT ? (sF0 + (kt & 1) * FSTRIDE) : (sR0 + (kt & 3) * 8704);
        #pragma unroll
        for (int ks = 0; ks < 2; ks++) {
            uint32_t aF[4][4], bF[2][4];
            #pragma unroll
            for (int mt = 0; mt < 4; mt++) {
                if (!OUTT) {
                    ldsm4(aF[mt], sA + (wm * 64 + mt * 16 + (lane & 15)) * 80
                                     + ((lane >> 4) + 2 * ks) * 16);
                } else {
                    ldsm4t(aF[mt], sA + ((lane & 7) + (lane >> 4) * 8 + 16 * ks) * 272
                                      + (wm * 64 + mt * 16 + ((lane >> 3) & 1) * 8) * 2);
                }
            }
            #pragma unroll
            for (int nt = 0; nt < 2; nt++)
                ldsm4t(bF[nt], sB + ((lane & 15) + 16 * ks) * 272
                                  + wn * 64 + nt * 32 + (lane >> 4) * 16);
            #pragma unroll
            for (int mt = 0; mt < 4; mt++)
                #pragma unroll
                for (int n8 = 0; n8 < 4; n8++)
                    mma16816(acc[mt][n8], aF[mt],
                             bF[n8 >> 1][(n8 & 1) * 2], bF[n8 >> 1][(n8 & 1) * 2 + 1]);
        }
    };

    // prologue
    ldF(0);
    #pragma unroll
    for (int s = 0; s < 3; s++) { cpR(s, s * 32); cp_commit(); }

    #pragma unroll 1
    for (int kt = 0; kt < 128; kt++) {
        stsF(kt & 1);
        if (kt + 1 < 128) ldF((kt + 1) * 32);   // hoisted: LDG issues before the wait
        cp_wait2();
        __syncthreads();
        const int nx = kt + 3;
        if (nx < 128) cpR(nx & 3, nx * 32);
        cp_commit();
        compute(kt);
    }

    const float s = 1.f / 4096.f;
    if (!OUTT) {
        #pragma unroll
        for (int mt = 0; mt < 4; mt++)
            #pragma unroll
            for (int n8 = 0; n8 < 4; n8++) {
                const int row = tile0 + wm * 64 + mt * 16 + g;
                const int col = wn * 32 + n8 * 8 + 2 * t;
                *(float2*)&updB[(long)row * 384 + col] =
                    make_float2(acc[mt][n8][0] * s, acc[mt][n8][1] * s);
                *(float2*)&updB[(long)(row + 8) * 384 + col] =
                    make_float2(acc[mt][n8][2] * s, acc[mt][n8][3] * s);
            }
    } else {
        __syncthreads();
        float* fsm = (float*)smem;   // [v][132] = 67584 B
        #pragma unroll
        for (int mt = 0; mt < 4; mt++)
            #pragma unroll
            for (int n8 = 0; n8 < 4; n8++) {
                const int v = wm * 64 + mt * 16 + g;
                const int j = wn * 32 + n8 * 8 + 2 * t;
                fsm[v * 132 + j]           = acc[mt][n8][0] * s;
                fsm[v * 132 + j + 1]       = acc[mt][n8][1] * s;
                fsm[(v + 8) * 132 + j]     = acc[mt][n8][2] * s;
                fsm[(v + 8) * 132 + j + 1] = acc[mt][n8][3] * s;
            }
        __syncthreads();
        const int j  = tid >> 1;
        const int vb = (tid & 1) * 64;
        float* dst = &updB[(long)(tile0 + j) * 384 + 256 + vb];
        #pragma unroll
        for (int i = 0; i < 16; i++) {
            const int v = vb + i * 4;
            ((float4*)dst)[i] = make_float4(
                fsm[v * 132 + j],       fsm[(v + 1) * 132 + j],
                fsm[(v + 2) * 132 + j], fsm[(v + 3) * 132 + j]);
        }
    }
}

__global__ __launch_bounds__(256, 2)
void agg_both(const float* __restrict__ adj,
              const __half* __restrict__ in_rep,
              const __half* __restrict__ out_rep,
              float* __restrict__ upd)
{
    extern __shared__ char smem[];
    if (blockIdx.z == 0) agg_body<false>(adj, in_rep,  upd, smem);
    else                 agg_body<true >(adj, out_rep, upd, smem);
}

// ===========================================================================
// R9 gemm_core (final kernel only): CTA 64x128, BK=32, TN.
// ===========================================================================
#define AROW 20
#define BROW 136

__global__ __launch_bounds__(256, 2)
void final_kernel(const float* __restrict__ upd, const float* __restrict__ W,
                  const float* __restrict__ bias, float* __restrict__ out)
{
    __shared__ uint32_t As[2][64][AROW];
    __shared__ uint32_t Bs[2][16][BROW];

    const int tid  = threadIdx.x;
    const int lane = tid & 31;
    const int warp = tid >> 5;
    const int wm   = warp >> 2;
    const int wn   = warp & 3;
    const int g    = lane >> 2;
    const int t    = lane & 3;
    const int m0   = blockIdx.x * 64;

    float acc[2][4][4];
    #pragma unroll
    for (int i = 0; i < 2; i++)
        #pragma unroll
        for (int j = 0; j < 4; j++)
            #pragma unroll
            for (int l = 0; l < 4; l++) acc[i][j][l] = 0.f;

    const int m_a = tid >> 2, q_a = tid & 3;
    const int kkw = tid & 15, nb = (tid >> 4) * 8;

    float fa[8];
    float2 rbf[8];

    auto loadRegs = [&](int k0) {
        const float4* p = (const float4*)(upd + (long)(m0 + m_a) * 384 + k0 + 8 * q_a);
        float4 v0 = p[0], v1 = p[1];
        fa[0] = v0.x; fa[1] = v0.y; fa[2] = v0.z; fa[3] = v0.w;
        fa[4] = v1.x; fa[5] = v1.y; fa[6] = v1.z; fa[7] = v1.w;
        #pragma unroll
        for (int i = 0; i < 8; i++)
            rbf[i] = *(const float2*)(W + (long)(nb + i) * 384 + k0 + 2 * kkw);
    };
    auto stsRegs = [&](int buf) {
        uint32_t w[4];
        #pragma unroll
        for (int i = 0; i < 4; i++) w[i] = pack2(fa[2 * i], fa[2 * i + 1]);
        *(uint4*)&As[buf][m_a][4 * q_a] = make_uint4(w[0], w[1], w[2], w[3]);
        uint32_t v[8];
        #pragma unroll
        for (int i = 0; i < 8; i++) v[i] = pack2(rbf[i].x, rbf[i].y);
        *(uint4*)&Bs[buf][kkw][nb]     = make_uint4(v[0], v[1], v[2], v[3]);
        *(uint4*)&Bs[buf][kkw][nb + 4] = make_uint4(v[4], v[5], v[6], v[7]);
    };
    auto compute = [&](int buf) {
        #pragma unroll
        for (int ks = 0; ks < 2; ks++) {
            const int k8 = ks * 8;
            uint32_t af[2][4];
            #pragma unroll
            for (int mt = 0; mt < 2; mt++) {
                const int mr = wm * 32 + mt * 16 + g;
                af[mt][0] = As[buf][mr][k8 + t];
                af[mt][1] = As[buf][mr + 8][k8 + t];
                af[mt][2] = As[buf][mr][k8 + t + 4];
                af[mt][3] = As[buf][mr + 8][k8 + t + 4];
            }
            #pragma unroll
            for (int nt = 0; nt < 4; nt++) {
                const int nc = wn * 32 + nt * 8 + g;
                mma16816(acc[0][nt], af[0], Bs[buf][k8 + t][nc], Bs[buf][k8 + t + 4][nc]);
                mma16816(acc[1][nt], af[1], Bs[buf][k8 + t][nc], Bs[buf][k8 + t + 4][nc]);
            }
        }
    };

    loadRegs(0);
    int buf = 0;
    for (int kt = 0; kt < 12; kt++) {
        stsRegs(buf);
        __syncthreads();
        if (kt + 1 < 12) loadRegs((kt + 1) * 32);
        compute(buf);
        buf ^= 1;
    }

    #pragma unroll
    for (int mt = 0; mt < 2; mt++) {
        #pragma unroll
        for (int nt = 0; nt < 4; nt++) {
            const int row = m0 + wm * 32 + mt * 16 + g;
            const int col = wn * 32 + nt * 8 + 2 * t;
            const float b0 = __ldg(bias + col);
            const float b1 = __ldg(bias + col + 1);
            float x0 = tanhf(acc[mt][nt][0] + b0), x1 = tanhf(acc[mt][nt][1] + b1);
            float x2 = tanhf(acc[mt][nt][2] + b0), x3 = tanhf(acc[mt][nt][3] + b1);
            *(float2*)&out[(long)row       * 128 + col] = make_float2(x0, x1);
            *(float2*)&out[(long)(row + 8) * 128 + col] = make_float2(x2, x3);
        }
    }
}

// ===========================================================================
extern "C" void kernel_launch(void* const* d_in, const int* in_sizes, int n_in,
                              void* d_out, int out_size)
{
    const float* nodes  = (const float*)d_in[0];
    const float* adj    = (const float*)d_in[1];
    const float* W_in   = (const float*)d_in[2];
    const float* b_in   = (const float*)d_in[3];
    const float* W_out  = (const float*)d_in[4];
    const float* b_out  = (const float*)d_in[5];
    const float* W_node = (const float*)d_in[6];
    const float* b_node = (const float*)d_in[7];
    const float* W_upd  = (const float*)d_in[8];
    const float* b_upd  = (const float*)d_in[9];
    float* out = (float*)d_out;

    __half *in_rep, *out_rep;
    float *upd;
    cudaGetSymbolAddress((void**)&in_rep,  g_in_rep);
    cudaGetSymbolAddress((void**)&out_rep, g_out_rep);
    cudaGetSymbolAddress((void**)&upd,     g_upd);

    const int SMEM_PROJ = 2 * 34816;      // 69632: A + one W, 2 CTA/SM
    const int SMEM_AGG  = 128 * 132 * 4;  // 67584
    cudaFuncSetAttribute(proj3_v2,
                         cudaFuncAttributeMaxDynamicSharedMemorySize, SMEM_PROJ);
    cudaFuncSetAttribute(agg_both,
                         cudaFuncAttributeMaxDynamicSharedMemorySize, SMEM_AGG);

    // 1) three ELU projections (one W per CTA, 2 CTA/SM)
    proj3_v2<<<dim3(128, 1, 3), 256, SMEM_PROJ>>>(nodes, W_in, b_in, W_node, b_node,
                                                  W_out, b_out, in_rep, out_rep, upd);

    // 2+3) both aggregations, one launch, fp32 adj direct
    agg_both<<<dim3(32, 4, 2), 256, SMEM_AGG>>>(adj, in_rep, out_rep, upd);

    // 4) out = tanh(upd @ W_upd^T + b_upd)
    final_kernel<<<256, 256>>>(upd, W_upd, b_upd, out);
}

// round 12
// speedup vs baseline: 1.6543x; 1.1058x over previous
#include <cuda_runtime.h>
#include <cuda_fp16.h>
#include <cstdint>
#include <cmath>

// ---------------------------------------------------------------------------
// GraphSageLayer: B=4, N=4096, D_IN=128, REP=128, D_OUT=128
//
//  conv_h  : nodes, W_in/W_node/W_out, W_upd -> fp16 (one tiny streaming pass)
//  proj3h  : fp16 x fp16 ELU projections (cp.async, K=128 resident)
//            in_rep/out_rep fp16; node_rep -> upd16[:,128:256] fp16
//  agg_both: (1 launch, z=2) fp32 adj direct, cvt in staging (R9 loop),
//            epilogues write upd16 fp16
//  final16 : fp16 x fp16 tanh GEMM over upd16, K=384, 4-stage cp.async
// ---------------------------------------------------------------------------

__device__ __half g_in_rep [4l * 4096 * 128];
__device__ __half g_out_rep[4l * 4096 * 128];
__device__ __half g_upd16  [4l * 4096 * 384];   // 12 MB
__device__ __half g_nodesh [16384l * 128];      // 4 MB
__device__ __half g_Wh     [3l * 128 * 128];    // z-order: in, node, out
__device__ __half g_Wupdh  [128l * 384];

__device__ __forceinline__ uint32_t pack2(float a, float b) {
    uint32_t r;
    asm("cvt.rn.f16x2.f32 %0, %1, %2;" : "=r"(r) : "f"(b), "f"(a));
    return r;
}
__device__ __forceinline__ void cp16(uint32_t dst, const void* src) {
    asm volatile("cp.async.cg.shared.global [%0], [%1], 16;" :: "r"(dst), "l"(src));
}
__device__ __forceinline__ void cp_commit() {
    asm volatile("cp.async.commit_group;");
}
__device__ __forceinline__ void cp_wait2() {
    asm volatile("cp.async.wait_group 2;");
}
__device__ __forceinline__ void cp_wait0() {
    asm volatile("cp.async.wait_group 0;");
}
__device__ __forceinline__ void ldsm4(uint32_t* r, uint32_t a) {
    asm volatile("ldmatrix.sync.aligned.m8n8.x4.shared.b16 {%0,%1,%2,%3}, [%4];"
        : "=r"(r[0]), "=r"(r[1]), "=r"(r[2]), "=r"(r[3]) : "r"(a));
}
__device__ __forceinline__ void ldsm4t(uint32_t* r, uint32_t a) {
    asm volatile("ldmatrix.sync.aligned.m8n8.x4.trans.shared.b16 {%0,%1,%2,%3}, [%4];"
        : "=r"(r[0]), "=r"(r[1]), "=r"(r[2]), "=r"(r[3]) : "r"(a));
}
__device__ __forceinline__ void mma16816(float* c, const uint32_t* a,
                                         uint32_t b0, uint32_t b1) {
    asm volatile(
        "mma.sync.aligned.m16n8k16.row.col.f32.f16.f16.f32 "
        "{%0,%1,%2,%3}, {%4,%5,%6,%7}, {%8,%9}, {%0,%1,%2,%3};\n"
        : "+f"(c[0]), "+f"(c[1]), "+f"(c[2]), "+f"(c[3])
        : "r"(a[0]), "r"(a[1]), "r"(a[2]), "r"(a[3]), "r"(b0), "r"(b1));
}

// ===========================================================================
// conv_h: fp32 -> fp16 for nodes + all weight matrices. 8 elems/thread.
// blocks [0,1024) nodes | [1024,1032) W_in | [1032,1040) W_node
// [1040,1048) W_out | [1048,1072) W_upd
// ===========================================================================
__global__ __launch_bounds__(256)
void conv_h(const float* __restrict__ nodes,
            const float* __restrict__ W_in, const float* __restrict__ W_node,
            const float* __restrict__ W_out, const float* __restrict__ W_upd,
            __half* __restrict__ nodesh, __half* __restrict__ Wh,
            __half* __restrict__ Wupdh)
{
    const int bx = blockIdx.x;
    const float* src; __half* dst; long g;
    if (bx < 1024)      { src = nodes;  dst = nodesh;            g = (long)bx * 256 + threadIdx.x; }
    else if (bx < 1032) { src = W_in;   dst = Wh;                g = (long)(bx - 1024) * 256 + threadIdx.x; }
    else if (bx < 1040) { src = W_node; dst = Wh + 16384;        g = (long)(bx - 1032) * 256 + threadIdx.x; }
    else if (bx < 1048) { src = W_out;  dst = Wh + 32768;        g = (long)(bx - 1040) * 256 + threadIdx.x; }
    else                { src = W_upd;  dst = Wupdh;             g = (long)(bx - 1048) * 256 + threadIdx.x; }
    float4 a = __ldcs((const float4*)src + 2 * g);
    float4 b = __ldcs((const float4*)src + 2 * g + 1);
    ((uint4*)dst)[g] = make_uint4(pack2(a.x, a.y), pack2(a.z, a.w),
                                  pack2(b.x, b.y), pack2(b.z, b.w));
}

// ===========================================================================
// proj3h: grid (256,1,3), 256 thr. CTA 64x128, K=128 fully resident fp16.
// smem: A (64 x 272B) @0, B (128 x 272B) @17408. Total 52224.
// ===========================================================================
__global__ __launch_bounds__(256, 2)
void proj3h(const __half* __restrict__ nodesh, const __half* __restrict__ Wh,
            const float* __restrict__ b_in, const float* __restrict__ b_node,
            const float* __restrict__ b_out,
            __half* __restrict__ in_rep, __half* __restrict__ out_rep,
            __half* __restrict__ upd16)
{
    extern __shared__ char sm[];
    const int tid  = threadIdx.x;
    const int lane = tid & 31;
    const int warp = tid >> 5;
    const int wm = warp >> 2, wn = warp & 3;
    const int g = lane >> 2, t = lane & 3;
    const int m0 = blockIdx.x * 64;
    const int z  = blockIdx.z;

    const __half* Wz  = Wh + z * 16384;
    const float* bias = (z == 0) ? b_in : (z == 1) ? b_node : b_out;

    const uint32_t sA = (uint32_t)__cvta_generic_to_shared(sm);
    const uint32_t sB = sA + 17408;

    // stage both operands (fp16, async)
    #pragma unroll
    for (int i = 0; i < 4; i++) {
        const int c = i * 256 + tid, row = c >> 4, ch = c & 15;
        cp16(sA + row * 272 + ch * 16, nodesh + (long)(m0 + row) * 128 + ch * 8);
    }
    #pragma unroll
    for (int i = 0; i < 8; i++) {
        const int c = i * 256 + tid, row = c >> 4, ch = c & 15;
        cp16(sB + row * 272 + ch * 16, Wz + (long)row * 128 + ch * 8);
    }
    cp_commit();
    cp_wait0();
    __syncthreads();

    float acc[2][4][4];
    #pragma unroll
    for (int i = 0; i < 2; i++)
        #pragma unroll
        for (int j = 0; j < 4; j++)
            #pragma unroll
            for (int l = 0; l < 4; l++) acc[i][j][l] = 0.f;

    #pragma unroll
    for (int k = 0; k < 8; k++) {
        const uint32_t kOff = ((lane >> 4) + 2 * k) * 16;
        uint32_t aF[2][4], bR[2][4];
        #pragma unroll
        for (int mt = 0; mt < 2; mt++)
            ldsm4(aF[mt], sA + (wm * 32 + mt * 16 + (lane & 15)) * 272 + kOff);
        #pragma unroll
        for (int i = 0; i < 2; i++)
            ldsm4(bR[i], sB + (wn * 32 + i * 16 + (lane & 15)) * 272 + kOff);
        #pragma unroll
        for (int mt = 0; mt < 2; mt++)
            #pragma unroll
            for (int nt = 0; nt < 4; nt++)
                mma16816(acc[mt][nt], aF[mt],
                         bR[nt >> 1][nt & 1], bR[nt >> 1][(nt & 1) + 2]);
    }

    #pragma unroll
    for (int mt = 0; mt < 2; mt++)
        #pragma unroll
        for (int nt = 0; nt < 4; nt++) {
            const int row = m0 + wm * 32 + mt * 16 + g;
            const int col = wn * 32 + nt * 8 + 2 * t;
            const float b0 = __ldg(bias + col), b1 = __ldg(bias + col + 1);
            float x0 = acc[mt][nt][0] + b0, x1 = acc[mt][nt][1] + b1;
            float x2 = acc[mt][nt][2] + b0, x3 = acc[mt][nt][3] + b1;
            x0 = x0 > 0.f ? x0 : expm1f(x0);
            x1 = x1 > 0.f ? x1 : expm1f(x1);
            x2 = x2 > 0.f ? x2 : expm1f(x2);
            x3 = x3 > 0.f ? x3 : expm1f(x3);
            if (z == 1) {
                *(uint32_t*)&upd16[(long)row       * 384 + 128 + col] = pack2(x0, x1);
                *(uint32_t*)&upd16[(long)(row + 8) * 384 + 128 + col] = pack2(x2, x3);
            } else {
                __half* D = (z == 0) ? in_rep : out_rep;
                *(uint32_t*)&D[(long)row       * 128 + col] = pack2(x0, x1);
                *(uint32_t*)&D[(long)(row + 8) * 128 + col] = pack2(x2, x3);
            }
        }
}

// ===========================================================================
// Aggregation (EXACT R9 loop): CTA 128x128, BK=32.
//  adj: fp32 LDG -> cvt(x4096) -> STS fp16, 2 smem bufs, reg-prefetch dist 1.
//  rep: fp16 cp.async, 4-stage. Epilogues write upd16 fp16.
// ===========================================================================
template<bool OUTT>
__device__ __forceinline__ void agg_body(
    const float* __restrict__ adj, const __half* __restrict__ rep,
    __half* __restrict__ upd, char* smem)
{
    const int tid  = threadIdx.x;
    const int lane = tid & 31;
    const int warp = tid >> 5;
    const int wm   = warp >> 2;
    const int wn   = warp & 3;
    const int g    = lane >> 2;
    const int t    = lane & 3;
    const int tile0 = blockIdx.x * 128;
    const long b   = blockIdx.y;

    const float*  adjB = adj + b * (4096l * 4096);
    const __half* repB = rep + b * (4096l * 128);
    __half*       updB = upd + b * (4096l * 384);

    const uint32_t smBase = (uint32_t)__cvta_generic_to_shared(smem);
    const uint32_t sF0 = OUTT ? (smBase + 34816) : smBase;
    const int      FSTRIDE = OUTT ? 8704 : 10240;
    const uint32_t sR0 = OUTT ? smBase : (smBase + 20480);

    float acc[4][4][4];
    #pragma unroll
    for (int i = 0; i < 4; i++)
        #pragma unroll
        for (int j = 0; j < 4; j++)
            #pragma unroll
            for (int l = 0; l < 4; l++) acc[i][j][l] = 0.f;

    const int f_row = OUTT ? (tid >> 3) : (tid >> 1);
    const int f_ch  = OUTT ? (tid & 7)  : (tid & 1);
    const float* fSrcBase = OUTT
        ? (adjB + (long)f_row * 4096 + tile0 + f_ch * 16)
        : (adjB + (long)(tile0 + f_row) * 4096 + f_ch * 16);
    const uint32_t fDst = (OUTT ? f_row * 272 : f_row * 80) + f_ch * 32;

    float4 fv[4];
    auto ldF = [&](int k0) {
        const float* p = OUTT ? (fSrcBase + (long)k0 * 4096) : (fSrcBase + k0);
        #pragma unroll
        for (int i = 0; i < 4; i++) fv[i] = ((const float4*)p)[i];
    };
    auto stsF = [&](int buf) {
        uint32_t w[8];
        #pragma unroll
        for (int i = 0; i < 4; i++) {
            w[2 * i]     = pack2(fv[i].x * 4096.f, fv[i].y * 4096.f);
            w[2 * i + 1] = pack2(fv[i].z * 4096.f, fv[i].w * 4096.f);
        }
        const uint32_t d = (sF0 - smBase) + buf * FSTRIDE + fDst;
        *(uint4*)(smem + d)      = make_uint4(w[0], w[1], w[2], w[3]);
        *(uint4*)(smem + d + 16) = make_uint4(w[4], w[5], w[6], w[7]);
    };

    const int r_k  = tid >> 4;
    const int r_nc = tid & 15;
    auto cpR = [&](int st, int k0) {
        const uint32_t sR = sR0 + st * 8704;
        cp16(sR + r_k * 272 + r_nc * 16,        repB + (long)(k0 + r_k) * 128 + r_nc * 8);
        cp16(sR + (r_k + 16) * 272 + r_nc * 16, repB + (long)(k0 + r_k + 16) * 128 + r_nc * 8);
    };

    auto compute = [&](int kt) {
        const uint32_t sA = OUTT ? (sR0 + (kt & 3) * 8704) : (sF0 + (kt & 1) * FSTRIDE);
        const uint32_t sB = OUTT ? (sF0 + (kt & 1) * FSTRIDE) : (sR0 + (kt & 3) * 8704);
        #pragma unroll
        for (int ks = 0; ks < 2; ks++) {
            uint32_t aF[4][4], bF[2][4];
            #pragma unroll
            for (int mt = 0; mt < 4; mt++) {
                if (!OUTT) {
                    ldsm4(aF[mt], sA + (wm * 64 + mt * 16 + (lane & 15)) * 80
                                     + ((lane >> 4) + 2 * ks) * 16);
                } else {
                    ldsm4t(aF[mt], sA + ((lane & 7) + (lane >> 4) * 8 + 16 * ks) * 272
                                      + (wm * 64 + mt * 16 + ((lane >> 3) & 1) * 8) * 2);
                }
            }
            #pragma unroll
            for (int nt = 0; nt < 2; nt++)
                ldsm4t(bF[nt], sB + ((lane & 15) + 16 * ks) * 272
                                  + wn * 64 + nt * 32 + (lane >> 4) * 16);
            #pragma unroll
            for (int mt = 0; mt < 4; mt++)
                #pragma unroll
                for (int n8 = 0; n8 < 4; n8++)
                    mma16816(acc[mt][n8], aF[mt],
                             bF[n8 >> 1][(n8 & 1) * 2], bF[n8 >> 1][(n8 & 1) * 2 + 1]);
        }
    };

    // prologue
    ldF(0);
    #pragma unroll
    for (int s = 0; s < 3; s++) { cpR(s, s * 32); cp_commit(); }

    #pragma unroll 1
    for (int kt = 0; kt < 128; kt++) {
        stsF(kt & 1);
        cp_wait2();
        __syncthreads();
        if (kt + 1 < 128) ldF((kt + 1) * 32);
        const int nx = kt + 3;
        if (nx < 128) cpR(nx & 3, nx * 32);
        cp_commit();
        compute(kt);
    }

    const float s = 1.f / 4096.f;
    if (!OUTT) {
        #pragma unroll
        for (int mt = 0; mt < 4; mt++)
            #pragma unroll
            for (int n8 = 0; n8 < 4; n8++) {
                const int row = tile0 + wm * 64 + mt * 16 + g;
                const int col = wn * 32 + n8 * 8 + 2 * t;
                *(uint32_t*)&updB[(long)row * 384 + col] =
                    pack2(acc[mt][n8][0] * s, acc[mt][n8][1] * s);
                *(uint32_t*)&updB[(long)(row + 8) * 384 + col] =
                    pack2(acc[mt][n8][2] * s, acc[mt][n8][3] * s);
            }
    } else {
        __syncthreads();
        float* fsm = (float*)smem;   // [v][132] = 67584 B
        #pragma unroll
        for (int mt = 0; mt < 4; mt++)
            #pragma unroll
            for (int n8 = 0; n8 < 4; n8++) {
                const int v = wm * 64 + mt * 16 + g;
                const int j = wn * 32 + n8 * 8 + 2 * t;
                fsm[v * 132 + j]           = acc[mt][n8][0] * s;
                fsm[v * 132 + j + 1]       = acc[mt][n8][1] * s;
                fsm[(v + 8) * 132 + j]     = acc[mt][n8][2] * s;
                fsm[(v + 8) * 132 + j + 1] = acc[mt][n8][3] * s;
            }
        __syncthreads();
        const int j  = tid >> 1;
        const int vb = (tid & 1) * 64;
        __half* dst = &updB[(long)(tile0 + j) * 384 + 256 + vb];
        #pragma unroll
        for (int i = 0; i < 16; i++) {
            const int v = vb + i * 4;
            *(uint2*)(dst + i * 4) = make_uint2(
                pack2(fsm[v * 132 + j],       fsm[(v + 1) * 132 + j]),
                pack2(fsm[(v + 2) * 132 + j], fsm[(v + 3) * 132 + j]));
        }
    }
}

__global__ __launch_bounds__(256, 2)
void agg_both(const float* __restrict__ adj,
              const __half* __restrict__ in_rep,
              const __half* __restrict__ out_rep,
              __half* __restrict__ upd16)
{
    extern __shared__ char smem[];
    if (blockIdx.z == 0) agg_body<false>(adj, in_rep,  upd16, smem);
    else                 agg_body<true >(adj, out_rep, upd16, smem);
}

// ===========================================================================
// final16: grid 256, CTA 64x128, K=384, 4-stage cp.async fp16 both operands.
// smem: 4 stages x (A 64x80 + B 128x80) = 4 x 15360 = 61440.
// ===========================================================================
__global__ __launch_bounds__(256, 2)
void final16(const __half* __restrict__ upd16, const __half* __restrict__ Wupdh,
             const float* __restrict__ bias, float* __restrict__ out)
{
    extern __shared__ char sm[];
    const int tid  = threadIdx.x;
    const int lane = tid & 31;
    const int warp = tid >> 5;
    const int wm = warp >> 2, wn = warp & 3;
    const int g = lane >> 2, t = lane & 3;
    const int m0 = blockIdx.x * 64;

    const uint32_t smBase = (uint32_t)__cvta_generic_to_shared(sm);

    float acc[2][4][4];
    #pragma unroll
    for (int i = 0; i < 2; i++)
        #pragma unroll
        for (int j = 0; j < 4; j++)
            #pragma unroll
            for (int l = 0; l < 4; l++) acc[i][j][l] = 0.f;

    auto cpStage = [&](int st, int k0) {
        const uint32_t sA = smBase + st * 15360;
        const uint32_t sB = sA + 5120;
        {   // A: 64 rows x 4 chunks = 256 (1/thread)
            const int row = tid >> 2, ch = tid & 3;
            cp16(sA + row * 80 + ch * 16, upd16 + (long)(m0 + row) * 384 + k0 + ch * 8);
        }
        #pragma unroll
        for (int i = 0; i < 2; i++) {   // B: 128 rows x 4 chunks = 512 (2/thread)
            const int c = i * 256 + tid, row = c >> 2, ch = c & 3;
            cp16(sB + row * 80 + ch * 16, Wupdh + (long)row * 384 + k0 + ch * 8);
        }
    };

    auto compute = [&](int st) {
        const uint32_t sA = smBase + st * 15360;
        const uint32_t sB = sA + 5120;
        #pragma unroll
        for (int ks = 0; ks < 2; ks++) {
            const uint32_t kOff = ((lane >> 4) + 2 * ks) * 16;
            uint32_t aF[2][4], bR[2][4];
            #pragma unroll
            for (int mt = 0; mt < 2; mt++)
                ldsm4(aF[mt], sA + (wm * 32 + mt * 16 + (lane & 15)) * 80 + kOff);
            #pragma unroll
            for (int i = 0; i < 2; i++)
                ldsm4(bR[i], sB + (wn * 32 + i * 16 + (lane & 15)) * 80 + kOff);
            #pragma unroll
            for (int mt = 0; mt < 2; mt++)
                #pragma unroll
                for (int nt = 0; nt < 4; nt++)
                    mma16816(acc[mt][nt], aF[mt],
                             bR[nt >> 1][nt & 1], bR[nt >> 1][(nt & 1) + 2]);
        }
    };

    #pragma unroll
    for (int s = 0; s < 3; s++) { cpStage(s, s * 32); cp_commit(); }

    #pragma unroll 1
    for (int kt = 0; kt < 12; kt++) {
        cp_wait2();
        __syncthreads();
        const int nx = kt + 3;
        if (nx < 12) cpStage(nx & 3, nx * 32);
        cp_commit();
        compute(kt & 3);
    }

    #pragma unroll
    for (int mt = 0; mt < 2; mt++)
        #pragma unroll
        for (int nt = 0; nt < 4; nt++) {
            const int row = m0 + wm * 32 + mt * 16 + g;
            const int col = wn * 32 + nt * 8 + 2 * t;
            const float b0 = __ldg(bias + col), b1 = __ldg(bias + col + 1);
            float x0 = tanhf(acc[mt][nt][0] + b0), x1 = tanhf(acc[mt][nt][1] + b1);
            float x2 = tanhf(acc[mt][nt][2] + b0), x3 = tanhf(acc[mt][nt][3] + b1);
            *(float2*)&out[(long)row       * 128 + col] = make_float2(x0, x1);
            *(float2*)&out[(long)(row + 8) * 128 + col] = make_float2(x2, x3);
        }
}

// ===========================================================================
extern "C" void kernel_launch(void* const* d_in, const int* in_sizes, int n_in,
                              void* d_out, int out_size)
{
    const float* nodes  = (const float*)d_in[0];
    const float* adj    = (const float*)d_in[1];
    const float* W_in   = (const float*)d_in[2];
    const float* b_in   = (const float*)d_in[3];
    const float* W_out  = (const float*)d_in[4];
    const float* b_out  = (const float*)d_in[5];
    const float* W_node = (const float*)d_in[6];
    const float* b_node = (const float*)d_in[7];
    const float* W_upd  = (const float*)d_in[8];
    const float* b_upd  = (const float*)d_in[9];
    float* out = (float*)d_out;

    __half *in_rep, *out_rep, *upd16, *nodesh, *Wh, *Wupdh;
    cudaGetSymbolAddress((void**)&in_rep,  g_in_rep);
    cudaGetSymbolAddress((void**)&out_rep, g_out_rep);
    cudaGetSymbolAddress((void**)&upd16,   g_upd16);
    cudaGetSymbolAddress((void**)&nodesh,  g_nodesh);
    cudaGetSymbolAddress((void**)&Wh,      g_Wh);
    cudaGetSymbolAddress((void**)&Wupdh,   g_Wupdh);

    const int SMEM_PROJ  = 52224;
    const int SMEM_AGG   = 128 * 132 * 4;  // 67584
    const int SMEM_FINAL = 61440;
    cudaFuncSetAttribute(proj3h,
                         cudaFuncAttributeMaxDynamicSharedMemorySize, SMEM_PROJ);
    cudaFuncSetAttribute(agg_both,
                         cudaFuncAttributeMaxDynamicSharedMemorySize, SMEM_AGG);
    cudaFuncSetAttribute(final16,
                         cudaFuncAttributeMaxDynamicSharedMemorySize, SMEM_FINAL);

    // 0) one-shot fp16 conversion of nodes + all weights
    conv_h<<<1072, 256>>>(nodes, W_in, W_node, W_out, W_upd, nodesh, Wh, Wupdh);

    // 1) three ELU projections (all-fp16 operands)
    proj3h<<<dim3(256, 1, 3), 256, SMEM_PROJ>>>(nodesh, Wh, b_in, b_node, b_out,
                                                in_rep, out_rep, upd16);

    // 2+3) both aggregations (fp32 adj direct; fp16 epilogue)
    agg_both<<<dim3(32, 4, 2), 256, SMEM_AGG>>>(adj, in_rep, out_rep, upd16);

    // 4) out = tanh(upd @ W_upd^T + b_upd)  (all-fp16 operands)
    final16<<<256, 256, SMEM_FINAL>>>(upd16, Wupdh, b_upd, out);
}